// round 8
// baseline (speedup 1.0000x reference)
#include <cuda_runtime.h>
#include <cuda_bf16.h>
#include <cstdint>

#define T_STEPS 512
#define BATCH   32
#define DIM     1024
#define NS      64
#define M_TOT   (T_STEPS * BATCH)   // 16384

// ---------------------------------------------------------------------------
// Device scratch
// ---------------------------------------------------------------------------
__device__ __align__(16) float  g_proj[(size_t)M_TOT * 256];   // [m][{k,q,v,ax}x64]
__device__ __align__(16) float4 g_kk[M_TOT];
__device__ __align__(16) __nv_bfloat16 g_Wh[256 * DIM];        // rows: k,q,v,ax
__device__ __align__(16) __nv_bfloat16 g_Wl[256 * DIM];

// ---------------------------------------------------------------------------
// helpers
// ---------------------------------------------------------------------------
__device__ __forceinline__ uint32_t smem_u32(const void* p) {
    uint32_t a;
    asm("{ .reg .u64 t; cvta.to.shared.u64 t, %1; cvt.u32.u64 %0, t; }" : "=r"(a) : "l"(p));
    return a;
}
__device__ __forceinline__ uint32_t bfpack(float hi_elem, float lo_elem) {
    uint32_t r;
    asm("cvt.rn.bf16x2.f32 %0, %1, %2;" : "=r"(r) : "f"(hi_elem), "f"(lo_elem));
    return r;
}
__device__ __forceinline__ uint32_t swoff(int row, int unit) {
    return (uint32_t)(row * 64 + ((unit ^ ((row >> 1) & 3)) << 4));
}
__device__ __forceinline__ void cp16(uint32_t dst, const void* src) {
    asm volatile("cp.async.cg.shared.global [%0], [%1], 16;" :: "r"(dst), "l"(src) : "memory");
}
__device__ __forceinline__ void ldsm4(uint32_t* r, uint32_t a) {
    asm volatile("ldmatrix.sync.aligned.m8n8.x4.shared.b16 {%0,%1,%2,%3}, [%4];"
                 : "=r"(r[0]), "=r"(r[1]), "=r"(r[2]), "=r"(r[3]) : "r"(a));
}
__device__ __forceinline__ void ldsm2(uint32_t* r, uint32_t a) {
    asm volatile("ldmatrix.sync.aligned.m8n8.x2.shared.b16 {%0,%1}, [%2];"
                 : "=r"(r[0]), "=r"(r[1]) : "r"(a));
}
__device__ __forceinline__ void mma16816(float* c, const uint32_t* a, const uint32_t* b) {
    asm volatile(
        "mma.sync.aligned.m16n8k16.row.col.f32.bf16.bf16.f32 "
        "{%0,%1,%2,%3}, {%4,%5,%6,%7}, {%8,%9}, {%0,%1,%2,%3};"
        : "+f"(c[0]), "+f"(c[1]), "+f"(c[2]), "+f"(c[3])
        : "r"(a[0]), "r"(a[1]), "r"(a[2]), "r"(a[3]), "r"(b[0]), "r"(b[1]));
}

// ---------------------------------------------------------------------------
// Weight prep: split 4x[64,1024] fp32 into bf16 hi/lo, row order k,q,v,ax
// ---------------------------------------------------------------------------
__global__ __launch_bounds__(256) void prep_w(
    const float* __restrict__ Wk, const float* __restrict__ Wq,
    const float* __restrict__ Wv, const float* __restrict__ Wa)
{
    int idx = blockIdx.x * 256 + threadIdx.x;
    int r = idx >> 8, c4 = idx & 255;
    const float* W = (r < 64) ? Wk : (r < 128) ? Wq : (r < 192) ? Wv : Wa;
    float4 v = ((const float4*)(W + (size_t)(r & 63) * DIM))[c4];
    uint32_t h01 = bfpack(v.y, v.x);
    uint32_t h23 = bfpack(v.w, v.z);
    float l0 = v.x - __uint_as_float(h01 << 16);
    float l1 = v.y - __uint_as_float(h01 & 0xffff0000u);
    float l2 = v.z - __uint_as_float(h23 << 16);
    float l3 = v.w - __uint_as_float(h23 & 0xffff0000u);
    ((uint2*)g_Wh)[idx] = make_uint2(h01, h23);
    ((uint2*)g_Wl)[idx] = make_uint2(bfpack(l1, l0), bfpack(l3, l2));
}

// ---------------------------------------------------------------------------
// Tensor-core projection GEMM (mma.sync bf16x3) — unchanged from R7 (passed)
// ---------------------------------------------------------------------------
#define STAGE_BYTES 49152
#define GEMM_SMEM   (2 * STAGE_BYTES)

__global__ __launch_bounds__(512) void proj_gemm_mma(const float* __restrict__ X)
{
    extern __shared__ char sm[];
    const uint32_t sb = smem_u32(sm);
    const int tid  = threadIdx.x;
    const int lane = tid & 31;
    const int wid  = tid >> 5;
    const int wm   = wid & 3;
    const int wn   = wid >> 2;
    const int m0   = blockIdx.x * 128;

    float c[2][8][4];
    #pragma unroll
    for (int i = 0; i < 2; i++)
        #pragma unroll
        for (int j = 0; j < 8; j++)
            #pragma unroll
            for (int q = 0; q < 4; q++) c[i][j][q] = 0.f;

    const int xrow = tid >> 2, xu = tid & 3;
    const int wp   = tid >> 8, wrow = tid & 255;

    auto issueW = [&](int ch, int s) {
        const __nv_bfloat16* src = (wp ? g_Wl : g_Wh) + (size_t)wrow * DIM + ch * 32;
        uint32_t dbase = sb + s * STAGE_BYTES + 16384 + wp * 16384;
        #pragma unroll
        for (int u = 0; u < 4; u++) cp16(dbase + swoff(wrow, u), src + u * 8);
        asm volatile("cp.async.commit_group;" ::: "memory");
    };
    float4 xa, xb;
    auto loadX = [&](int ch) {
        const float* p = X + (size_t)(m0 + xrow) * DIM + ch * 32 + xu * 8;
        xa = *(const float4*)p;
        xb = *(const float4*)(p + 4);
    };
    auto stsX = [&](int s) {
        uint32_t h01 = bfpack(xa.y, xa.x), h23 = bfpack(xa.w, xa.z);
        uint32_t h45 = bfpack(xb.y, xb.x), h67 = bfpack(xb.w, xb.z);
        float l0 = xa.x - __uint_as_float(h01 << 16);
        float l1 = xa.y - __uint_as_float(h01 & 0xffff0000u);
        float l2 = xa.z - __uint_as_float(h23 << 16);
        float l3 = xa.w - __uint_as_float(h23 & 0xffff0000u);
        float l4 = xb.x - __uint_as_float(h45 << 16);
        float l5 = xb.y - __uint_as_float(h45 & 0xffff0000u);
        float l6 = xb.z - __uint_as_float(h67 << 16);
        float l7 = xb.w - __uint_as_float(h67 & 0xffff0000u);
        uint32_t off = s * STAGE_BYTES + swoff(xrow, xu);
        *(uint4*)(sm + off)        = make_uint4(h01, h23, h45, h67);
        *(uint4*)(sm + off + 8192) = make_uint4(bfpack(l1, l0), bfpack(l3, l2),
                                                bfpack(l5, l4), bfpack(l7, l6));
    };

    issueW(0, 0);
    loadX(0);

    for (int ch = 0; ch < 32; ch++) {
        const int s = ch & 1;
        asm volatile("cp.async.wait_group 0;" ::: "memory");
        stsX(s);
        if (ch + 1 < 32) { issueW(ch + 1, s ^ 1); loadX(ch + 1); }
        __syncthreads();

        const uint32_t st = sb + s * STAGE_BYTES;
        #pragma unroll
        for (int kt = 0; kt < 2; kt++) {
            uint32_t ah[2][4], al[2][4];
            #pragma unroll
            for (int mt = 0; mt < 2; mt++) {
                uint32_t aoff = swoff(wm * 32 + mt * 16 + (lane & 15), kt * 2 + (lane >> 4));
                ldsm4(ah[mt], st + aoff);
                ldsm4(al[mt], st + 8192 + aoff);
            }
            #pragma unroll
            for (int nt = 0; nt < 8; nt++) {
                uint32_t boff = swoff(wn * 64 + nt * 8 + (lane & 7),
                                      kt * 2 + ((lane >> 3) & 1));
                uint32_t bh[2], bl[2];
                ldsm2(bh, st + 16384 + boff);
                ldsm2(bl, st + 32768 + boff);
                mma16816(c[0][nt], ah[0], bh);
                mma16816(c[1][nt], ah[1], bh);
                mma16816(c[0][nt], al[0], bh);
                mma16816(c[1][nt], al[1], bh);
                mma16816(c[0][nt], ah[0], bl);
                mma16816(c[1][nt], ah[1], bl);
            }
        }
        __syncthreads();
    }

    #pragma unroll
    for (int mt = 0; mt < 2; mt++) {
        #pragma unroll
        for (int nt = 0; nt < 8; nt++) {
            int m = m0 + wm * 32 + mt * 16 + (lane >> 2);
            int n = wn * 64 + nt * 8 + (lane & 3) * 2;
            *(float2*)&g_proj[(size_t)m * 256 + n]       = make_float2(c[mt][nt][0], c[mt][nt][1]);
            *(float2*)&g_proj[(size_t)(m + 8) * 256 + n] = make_float2(c[mt][nt][2], c[mt][nt][3]);
        }
    }
}

// ---------------------------------------------------------------------------
// kk kernel: g_kk[t][b] = {k_t·k_{t+1}, k_t·k_{t+2}, k_t·k_{t+3}, 0}
// ---------------------------------------------------------------------------
__global__ __launch_bounds__(128) void kk_kernel()
{
    int idx = blockIdx.x * 128 + threadIdx.x;
    int t = idx >> 5, b = idx & 31;
    const float4* p0 = (const float4*)(g_proj + (size_t)(t * 32 + b) * 256);
    int t1 = (t + 1 < T_STEPS) ? t + 1 : t;
    int t2 = (t + 2 < T_STEPS) ? t + 2 : t;
    int t3 = (t + 3 < T_STEPS) ? t + 3 : t;
    const float4* p1 = (const float4*)(g_proj + (size_t)(t1 * 32 + b) * 256);
    const float4* p2 = (const float4*)(g_proj + (size_t)(t2 * 32 + b) * 256);
    const float4* p3 = (const float4*)(g_proj + (size_t)(t3 * 32 + b) * 256);
    float a1 = 0.f, a2 = 0.f, a3 = 0.f;
    #pragma unroll
    for (int i = 0; i < 16; i++) {
        float4 k0 = p0[i], q1 = p1[i], q2 = p2[i], q3 = p3[i];
        a1 += k0.x*q1.x + k0.y*q1.y + k0.z*q1.z + k0.w*q1.w;
        a2 += k0.x*q2.x + k0.y*q2.y + k0.z*q2.z + k0.w*q2.w;
        a3 += k0.x*q3.x + k0.y*q3.y + k0.z*q3.z + k0.w*q3.w;
    }
    if (t + 1 >= T_STEPS) a1 = 0.f;
    if (t + 2 >= T_STEPS) a2 = 0.f;
    if (t + 3 >= T_STEPS) a3 = 0.f;
    g_kk[idx] = make_float4(a1, a2, a3, 0.f);
}

// ---------------------------------------------------------------------------
// Scan v3: sigma-affine recurrence + cp.async smem ring (depth 16).
// Critical chain per step: x -> sigmoid (MUFU chain) -> x' = fma(sg,px,qx).
// All other updates are single-FMA-after-sigma; reductions have a step of slack.
// Grid: 128 CTAs (4 per batch, 16 rows each) x 128 threads.
// Ring slot (192 floats): k[0..64) q[64..128) v[128..144) ax[144..160) kk[160..164)
// ---------------------------------------------------------------------------
#define RING 16
#define SLOTF 192

__global__ __launch_bounds__(128) void scan_kernel(
    const float* __restrict__ S_in,
    const float* __restrict__ d_alpha,
    const float* __restrict__ b_alpha,
    float* __restrict__ out)
{
    __shared__ __align__(16) float ring[RING * SLOTF];

    const int b   = blockIdx.x >> 2;
    const int rg  = blockIdx.x & 3;
    const int tid = threadIdx.x;
    const int rl  = tid >> 3;        // 0..15
    const int g   = tid & 7;         // 0..7
    const int row = rg * 16 + rl;
    const int c0  = g * 8;

    const uint32_t smb = smem_u32(ring);

    // cp.async producer roles
    auto issue_cp = [&](int slot, int gu) {
        if (gu > T_STEPS - 1) gu = T_STEPS - 1;
        const float* base = g_proj + (size_t)(gu * 32 + b) * 256;
        uint32_t dst = smb + slot * (SLOTF * 4);
        if (tid < 16)       cp16(dst + tid * 16,              base + tid * 4);
        else if (tid < 32)  cp16(dst + 256 + (tid - 16) * 16, base + 64 + (tid - 16) * 4);
        else if (tid < 36)  cp16(dst + 512 + (tid - 32) * 16, base + 128 + rg * 16 + (tid - 32) * 4);
        else if (tid < 40)  cp16(dst + 576 + (tid - 36) * 16, base + 192 + rg * 16 + (tid - 36) * 4);
        else if (tid == 40) cp16(dst + 640, (const float*)&g_kk[gu * 32 + b]);
        asm volatile("cp.async.commit_group;" ::: "memory");
    };

    // fill the ring
    #pragma unroll
    for (int u = 0; u < RING; u++) issue_cp(u, u);

    float S[8];
    {
        const float* sp = S_in + ((size_t)b * NS + row) * NS + c0;
        #pragma unroll
        for (int j = 0; j < 8; j++) S[j] = sp[j];
    }
    const float da = d_alpha[row];
    const float ba = b_alpha[row];

    auto red8 = [](float v) {
        v += __shfl_xor_sync(0xffffffffu, v, 1);
        v += __shfl_xor_sync(0xffffffffu, v, 2);
        v += __shfl_xor_sync(0xffffffffu, v, 4);
        return v;
    };

    asm volatile("cp.async.wait_group %0;" :: "n"(RING - 6) : "memory");
    __syncthreads();   // slots 0..5 visible to all threads

    // step-0 consumables + initial lookaheads from slots 0..5
    float kc[8], qc[8], k4c[8], vc, kk1, kk2, kk3, axbn;
    {
        const float4* p0 = (const float4*)&ring[0 * SLOTF + c0];
        float4 a0 = p0[0], a1v = p0[1];
        kc[0]=a0.x; kc[1]=a0.y; kc[2]=a0.z; kc[3]=a0.w;
        kc[4]=a1v.x; kc[5]=a1v.y; kc[6]=a1v.z; kc[7]=a1v.w;
        const float4* q0 = (const float4*)&ring[0 * SLOTF + 64 + c0];
        float4 b0 = q0[0], b1 = q0[1];
        qc[0]=b0.x; qc[1]=b0.y; qc[2]=b0.z; qc[3]=b0.w;
        qc[4]=b1.x; qc[5]=b1.y; qc[6]=b1.z; qc[7]=b1.w;
        const float4* p4 = (const float4*)&ring[4 * SLOTF + c0];
        float4 c4v = p4[0], c5 = p4[1];
        k4c[0]=c4v.x; k4c[1]=c4v.y; k4c[2]=c4v.z; k4c[3]=c4v.w;
        k4c[4]=c5.x; k4c[5]=c5.y; k4c[6]=c5.z; k4c[7]=c5.w;
        vc = ring[0 * SLOTF + 128 + rl];
        float4 kkv = *(const float4*)&ring[0 * SLOTF + 160];
        kk1 = kkv.x; kk2 = kkv.y; kk3 = kkv.z;
        axbn = ring[1 * SLOTF + 144 + rl] + ba;   // AxB_1 for step 0's qx
    }

    // initial r, A1..A3 vs S_init using k_0..k_3
    float x, A1, A2, A3;
    {
        float t0 = 0.f, t1 = 0.f, t2 = 0.f, t3 = 0.f;
        #pragma unroll
        for (int j = 0; j < 8; j++) {
            float k1v = ring[1 * SLOTF + c0 + j];
            float k2v = ring[2 * SLOTF + c0 + j];
            float k3v = ring[3 * SLOTF + c0 + j];
            t0 = fmaf(S[j], kc[j], t0);
            t1 = fmaf(S[j], k1v, t1);
            t2 = fmaf(S[j], k2v, t2);
            t3 = fmaf(S[j], k3v, t3);
        }
        float r0 = red8(t0);
        A1 = red8(t1); A2 = red8(t2); A3 = red8(t3);
        float axb0 = ring[0 * SLOTF + 144 + rl] + ba;
        x = fmaf(da, r0, axb0);
    }

    float* outp = out + (size_t)b * NS + row;

    #pragma unroll 2
    for (int t = 0; t < T_STEPS; t++) {
        // ---- pre-sigma (independent of sg) ----
        float vk1 = vc * kk1, vk2 = vc * kk2, vk3 = vc * kk3;
        float uA1 = A1 - vk1, uA2 = A2 - vk2, uA3 = A3 - vk3;
        float px  = da * uA1;
        float qx  = fmaf(da, vk1, axbn);
        float tj[8], uj[8];
        #pragma unroll
        for (int j = 0; j < 8; j++) { tj[j] = vc * kc[j]; uj[j] = S[j] - tj[j]; }

        // ---- critical chain ----
        float sg = __fdividef(1.f, 1.f + __expf(-x));
        x = fmaf(sg, px, qx);                       // x_{t+1}

        // ---- sigma-affine updates ----
        A1 = fmaf(sg, uA2, vk2);
        A2 = fmaf(sg, uA3, vk3);
        float h0 = 0.f, h1 = 0.f, d0 = 0.f, d1 = 0.f;
        #pragma unroll
        for (int j = 0; j < 8; j++) {
            float s = fmaf(sg, uj[j], tj[j]);
            S[j] = s;
            if (j & 1) { h1 = fmaf(s, qc[j], h1); d1 = fmaf(s, k4c[j], d1); }
            else       { h0 = fmaf(s, qc[j], h0); d0 = fmaf(s, k4c[j], d0); }
        }
        float h = h0 + h1, d = d0 + d1;
        h += __shfl_xor_sync(0xffffffffu, h, 1); d += __shfl_xor_sync(0xffffffffu, d, 1);
        h += __shfl_xor_sync(0xffffffffu, h, 2); d += __shfl_xor_sync(0xffffffffu, d, 2);
        h += __shfl_xor_sync(0xffffffffu, h, 4); d += __shfl_xor_sync(0xffffffffu, d, 4);
        A3 = d;                                    // S_t . k_{t+4}

        if (g == 0) {
            float sh = __fdividef(1.f, 1.f + __expf(-h));
            outp[0] = h * h * sh;                  // h * silu(h)
        }
        outp += BATCH * NS;

        // ---- stage next step from the ring ----
        asm volatile("cp.async.wait_group %0;" :: "n"(RING - 6) : "memory");
        __syncthreads();
        {
            int s1 = ((t + 1) & (RING - 1)) * SLOTF;
            int s2 = ((t + 2) & (RING - 1)) * SLOTF;
            int s5 = ((t + 5) & (RING - 1)) * SLOTF;
            const float4* pk = (const float4*)&ring[s1 + c0];
            float4 a0 = pk[0], a1v = pk[1];
            kc[0]=a0.x; kc[1]=a0.y; kc[2]=a0.z; kc[3]=a0.w;
            kc[4]=a1v.x; kc[5]=a1v.y; kc[6]=a1v.z; kc[7]=a1v.w;
            const float4* pq = (const float4*)&ring[s1 + 64 + c0];
            float4 b0 = pq[0], b1 = pq[1];
            qc[0]=b0.x; qc[1]=b0.y; qc[2]=b0.z; qc[3]=b0.w;
            qc[4]=b1.x; qc[5]=b1.y; qc[6]=b1.z; qc[7]=b1.w;
            const float4* p5 = (const float4*)&ring[s5 + c0];
            float4 e0 = p5[0], e1 = p5[1];
            k4c[0]=e0.x; k4c[1]=e0.y; k4c[2]=e0.z; k4c[3]=e0.w;
            k4c[4]=e1.x; k4c[5]=e1.y; k4c[6]=e1.z; k4c[7]=e1.w;
            vc = ring[s1 + 128 + rl];
            float4 kkv = *(const float4*)&ring[s1 + 160];
            kk1 = kkv.x; kk2 = kkv.y; kk3 = kkv.z;
            axbn = ring[s2 + 144 + rl] + ba;
        }
        issue_cp((t + RING) & (RING - 1), t + RING);
    }

    // S_final
    float* sf = out + (size_t)T_STEPS * BATCH * NS + ((size_t)b * NS + row) * NS + c0;
    #pragma unroll
    for (int j = 0; j < 8; j++) sf[j] = S[j];
}

// ---------------------------------------------------------------------------
extern "C" void kernel_launch(void* const* d_in, const int* in_sizes, int n_in,
                              void* d_out, int out_size) {
    const float* x  = (const float*)d_in[0];
    const float* S  = (const float*)d_in[1];
    const float* Wk = (const float*)d_in[2];
    const float* Wv = (const float*)d_in[3];
    const float* Wq = (const float*)d_in[4];
    const float* Wa = (const float*)d_in[5];
    const float* da = (const float*)d_in[6];
    const float* ba = (const float*)d_in[7];
    float* out = (float*)d_out;

    cudaFuncSetAttribute(proj_gemm_mma, cudaFuncAttributeMaxDynamicSharedMemorySize, GEMM_SMEM);

    prep_w<<<256, 256>>>(Wk, Wq, Wv, Wa);
    proj_gemm_mma<<<M_TOT / 128, 512, GEMM_SMEM>>>(x);
    kk_kernel<<<M_TOT / 128, 128>>>();
    scan_kernel<<<BATCH * 4, 128>>>(S, da, ba, out);
}